// round 7
// baseline (speedup 1.0000x reference)
#include <cuda_runtime.h>
#include <stdint.h>

// MultiEchoNeighborBlock: per-pixel 7x7 KNN (k=9) over point distances,
// gather range values in exact rank order, 20->32 linear + leaky relu.
//
// Shapes: x (4, 8, 64, 2048) f32   [ch0,ch1 = ranges; ch2-4 = pts echo0; ch5-7 = pts echo1]
//         range_weight (1, 32, 20) f32
//         out (4, 32, 64, 2048) f32
//
// R7 == R6 resubmit (R6 bench was an infra failure, no data).
// R6 vs R5 (156.0us, alu=79.7%, occ=34.5%, regs=74): pure saturation round.
//  - __launch_bounds__(TPB, 4): cap regs at 64 -> 4 blocks/SM -> 32 warps
//    (occ 50%) to hide the serial 9-stage ALU dependence chains.
//  - leaky-relu as fmaxf(v, 0.01v): FMNMX instead of FSETP+SEL.
// Sort algorithm unchanged (sticky-predicate stable insert, proven exact:
// rel_err 9.6e-8 identical to the unique-u64-key variant).

#define HH 64
#define WW 2048
#define HWP (HH * WW)
#define NCH 8
#define BX 128        // pixels along W per block
#define BY 2          // rows per block
#define TPB (BX * BY)
#define TW (BX + 6)   // tile width  (halo 3 each side)
#define TH (BY + 6)   // tile height

// Branchless stable insert of (kin, vin) into ascending sorted ak[0..8].
// Every comparison is (original kin < resident); since ak stays sorted the
// predicate is monotone in j, equivalent to the sticky-OR form (FSETP.OR
// fuses it anyway). Ties: incoming (later patch index) never displaces an
// equal resident; displaced residents shift without re-comparison -> exact
// top_k stable order. 1 FSETP + 4 SEL per stage.
__device__ __forceinline__ void ins9s(float kin, float vin,
                                      float (&ak)[9], float (&av)[9]) {
    bool p = false;
    float ck = kin, cv = vin;
#pragma unroll
    for (int j = 0; j < 9; ++j) {
        p = p | (kin < ak[j]);
        float tk = ak[j], tv = av[j];
        ak[j] = p ? ck : tk;
        av[j] = p ? cv : tv;
        ck = p ? tk : ck;
        cv = p ? tv : cv;
    }
}

__global__ __launch_bounds__(TPB, 4)
void knn_block_kernel(const float* __restrict__ x,
                      const float* __restrict__ rw,
                      float* __restrict__ out) {
    __shared__ float4 tile[TH][TW];   // (px, py, pz, range_ch0)
    __shared__ float wt[20][32];      // transposed weights: wt[c][k]

    const int tid = threadIdx.x;
    const int b = blockIdx.z;
    const int h0 = blockIdx.y * BY;
    const int w0 = blockIdx.x * BX;
    const float* X = x + (size_t)b * NCH * HWP;

    // Load + transpose weights (W[k,c] row-major -> wt[c][k]).
    for (int i = tid; i < 640; i += TPB) {
        wt[i % 20][i / 20] = rw[i];
    }
    // Load tile: channels 2,3,4 (points) + channel 0 (range), zero-padded.
    for (int i = tid; i < TH * TW; i += TPB) {
        int r = i / TW, c = i % TW;
        int gh = h0 - 3 + r, gw = w0 - 3 + c;
        float4 v = make_float4(0.f, 0.f, 0.f, 0.f);
        if (gh >= 0 && gh < HH && gw >= 0 && gw < WW) {
            int o = gh * WW + gw;
            v.x = X[2 * HWP + o];
            v.y = X[3 * HWP + o];
            v.z = X[4 * HWP + o];
            v.w = X[0 * HWP + o];
        }
        tile[r][c] = v;
    }
    __syncthreads();

    const int tx = tid % BX;
    const int ty = tid / BX;
    const int h = h0 + ty;
    const int w = w0 + tx;
    const int pix = h * WW + w;

    const float4 c4 = tile[ty + 3][tx + 3];
    const float q0x = c4.x, q0y = c4.y, q0z = c4.z;
    const float q1x = X[5 * HWP + pix];
    const float q1y = X[6 * HWP + pix];
    const float q1z = X[7 * HWP + pix];
    const float r1c = X[1 * HWP + pix];

    const float INF = __int_as_float(0x7f800000);
    float ak0[9], av0[9], ak1[9], av1[9];
#pragma unroll
    for (int j = 0; j < 9; ++j) {
        ak0[j] = INF; av0[j] = 0.f;
        ak1[j] = INF; av1[j] = 0.f;
    }

#pragma unroll 1
    for (int dy = 0; dy < 7; ++dy) {
        const float4* row = &tile[ty + dy][tx];
#pragma unroll
        for (int dx = 0; dx < 7; ++dx) {
            float4 p = row[dx];

            // Echo 0 distance: no FMA contraction (match XLA mul/add rounding),
            // IEEE sqrt (match jnp.sqrt) so ordering is bit-identical.
            float d0x = __fadd_rn(q0x, -p.x);
            float d0y = __fadd_rn(q0y, -p.y);
            float d0z = __fadd_rn(q0z, -p.z);
            float s0 = __fadd_rn(__fadd_rn(__fmul_rn(d0x, d0x), __fmul_rn(d0y, d0y)),
                                 __fmul_rn(d0z, d0z));
            float dist0 = __fsqrt_rn(s0);
            ins9s(dist0, p.w, ak0, av0);

            // Echo 1
            float d1x = __fadd_rn(q1x, -p.x);
            float d1y = __fadd_rn(q1y, -p.y);
            float d1z = __fadd_rn(q1z, -p.z);
            float s1 = __fadd_rn(__fadd_rn(__fmul_rn(d1x, d1x), __fmul_rn(d1y, d1y)),
                                 __fmul_rn(d1z, d1z));
            float dist1 = __fsqrt_rn(s1);
            ins9s(dist1, p.w, ak1, av1);
        }
    }

    // Features: payloads already sorted in rank order — no gather needed.
    float feats[20];
#pragma unroll
    for (int s = 0; s < 9; ++s) {
        feats[s]      = av0[s];
        feats[10 + s] = av1[s];
    }
    feats[9]  = c4.w;  // center range ch0
    feats[19] = r1c;   // center range ch1

    // 20 -> 32 linear
    float acc[32];
#pragma unroll
    for (int k = 0; k < 32; ++k) acc[k] = 0.f;
#pragma unroll
    for (int c = 0; c < 20; ++c) {
        float f = feats[c];
        const float4* wp = (const float4*)&wt[c][0];
#pragma unroll
        for (int k4 = 0; k4 < 8; ++k4) {
            float4 wv = wp[k4];
            acc[k4 * 4 + 0] += f * wv.x;
            acc[k4 * 4 + 1] += f * wv.y;
            acc[k4 * 4 + 2] += f * wv.z;
            acc[k4 * 4 + 3] += f * wv.w;
        }
    }

    float* O = out + (size_t)b * 32 * HWP + pix;
#pragma unroll
    for (int k = 0; k < 32; ++k) {
        float v = acc[k];
        // leaky_relu(0.01): for v>=0 max(v,0.01v)=v, for v<0 -> 0.01v.
        v = fmaxf(v, 0.01f * v);
        O[(size_t)k * HWP] = v;
    }
}

extern "C" void kernel_launch(void* const* d_in, const int* in_sizes, int n_in,
                              void* d_out, int out_size) {
    const float* x  = (const float*)d_in[0];
    const float* rw = (const float*)d_in[1];
    // Defensive: identify the 640-element weight tensor by size.
    if (n_in >= 2 && in_sizes[0] == 640) {
        const float* t = x; x = rw; rw = t;
    }
    dim3 grid(WW / BX, HH / BY, 4);
    knn_block_kernel<<<grid, TPB>>>(x, rw, (float*)d_out);
}

// round 9
// speedup vs baseline: 1.0503x; 1.0503x over previous
#include <cuda_runtime.h>
#include <stdint.h>

// MultiEchoNeighborBlock: per-pixel 7x7 KNN (k=9) over point distances,
// gather range values in exact rank order, 20->32 linear + leaky relu.
//
// Shapes: x (4, 8, 64, 2048) f32   [ch0,ch1 = ranges; ch2-4 = pts echo0; ch5-7 = pts echo1]
//         range_weight (1, 32, 20) f32
//         out (4, 32, 64, 2048) f32
//
// R9 == R8 resubmit (R8 bench was an infra failure, no data).
// R8 vs R5/R7: pipe rebalance. Evidence: alu pipe plateaus at 79.6% at BOTH
// occ 34.5% and 44.5% while fma sits at 17% -> alu issue is the wall and
// FSETP/SEL/FMNMX all live there. Fix: echo0's insert moves payload selection
// to the fma pipe (FSET float mask + FFMA blends); keys use the FMNMX
// insertion identity. Echo1 keeps the proven alu sticky-insert. Per pixel:
// alu ~4700 -> ~3450, fma ~1400 -> ~3200 (balanced).
// Ordering math unchanged: masks/compares use the ORIGINAL incoming key
// (stable tie semantics proven in R5, rel_err 9.598e-8). FFMA payload blends
// are value-moves (m in {0,1}); worst case 1-ulp payload noise, never an
// ordering decision. Occupancy clamp reverted (R7 showed it was a 2% loss).

#define HH 64
#define WW 2048
#define HWP (HH * WW)
#define NCH 8
#define BX 128        // pixels along W per block
#define BY 2          // rows per block
#define TPB (BX * BY)
#define TW (BX + 6)   // tile width  (halo 3 each side)
#define TH (BY + 6)   // tile height

// alu-flavor: branchless stable insert (kin,vin) into ascending ak[0..8].
// 1 FSETP + 4 SEL per stage. Ties: incoming sinks below equal residents;
// displaced residents never re-compared -> exact top_k stable order.
__device__ __forceinline__ void ins9_alu(float kin, float vin,
                                         float (&ak)[9], float (&av)[9]) {
    bool p = false;
    float ck = kin, cv = vin;
#pragma unroll
    for (int j = 0; j < 9; ++j) {
        p = p | (kin < ak[j]);
        float tk = ak[j], tv = av[j];
        ak[j] = p ? ck : tk;
        av[j] = p ? cv : tv;
        ck = p ? tk : ck;
        cv = p ? tv : cv;
    }
}

// fma-flavor: same insert semantics, payload path on the fma pipe.
// Keys: running-carry min/max identity (2 FMNMX, alu).
//   ak_new[j] = min(c_j, ak_old[j]); c_{j+1} = max(c_j, ak_old[j]), c_0 = kin.
// Payload: m_j = (kin < ak_old[j]) ? 1.0f : 0.0f  (FSET, exact {0,1});
//   diff = cv - av[j]; av[j] += m*diff; cv -= m*diff  (FADD + 2 FFMA).
// m_j is monotone in j (array sorted), identical to the sticky predicate.
__device__ __forceinline__ void ins9_fma(float kin, float vin,
                                         float (&ak)[9], float (&av)[9]) {
    float ck = kin, cv = vin;
#pragma unroll
    for (int j = 0; j < 9; ++j) {
        float aj = ak[j];
        float m;
        asm("set.lt.f32.f32 %0, %1, %2;" : "=f"(m) : "f"(kin), "f"(aj));
        float mn = fminf(ck, aj);
        float mx = fmaxf(ck, aj);
        float diff = __fadd_rn(cv, -av[j]);
        av[j] = __fmaf_rn(m, diff, av[j]);   // m ? cv : av[j]  (±1ulp ok)
        cv    = __fmaf_rn(-m, diff, cv);     // m ? av_old[j] : cv
        ak[j] = mn;
        ck = mx;
    }
}

__global__ __launch_bounds__(TPB)
void knn_block_kernel(const float* __restrict__ x,
                      const float* __restrict__ rw,
                      float* __restrict__ out) {
    __shared__ float4 tile[TH][TW];   // (px, py, pz, range_ch0)
    __shared__ float wt[20][32];      // transposed weights: wt[c][k]

    const int tid = threadIdx.x;
    const int b = blockIdx.z;
    const int h0 = blockIdx.y * BY;
    const int w0 = blockIdx.x * BX;
    const float* X = x + (size_t)b * NCH * HWP;

    // Load + transpose weights (W[k,c] row-major -> wt[c][k]).
    for (int i = tid; i < 640; i += TPB) {
        wt[i % 20][i / 20] = rw[i];
    }
    // Load tile: channels 2,3,4 (points) + channel 0 (range), zero-padded.
    for (int i = tid; i < TH * TW; i += TPB) {
        int r = i / TW, c = i % TW;
        int gh = h0 - 3 + r, gw = w0 - 3 + c;
        float4 v = make_float4(0.f, 0.f, 0.f, 0.f);
        if (gh >= 0 && gh < HH && gw >= 0 && gw < WW) {
            int o = gh * WW + gw;
            v.x = X[2 * HWP + o];
            v.y = X[3 * HWP + o];
            v.z = X[4 * HWP + o];
            v.w = X[0 * HWP + o];
        }
        tile[r][c] = v;
    }
    __syncthreads();

    const int tx = tid % BX;
    const int ty = tid / BX;
    const int h = h0 + ty;
    const int w = w0 + tx;
    const int pix = h * WW + w;

    const float4 c4 = tile[ty + 3][tx + 3];
    const float q0x = c4.x, q0y = c4.y, q0z = c4.z;
    const float q1x = X[5 * HWP + pix];
    const float q1y = X[6 * HWP + pix];
    const float q1z = X[7 * HWP + pix];
    const float r1c = X[1 * HWP + pix];

    const float INF = __int_as_float(0x7f800000);
    float ak0[9], av0[9], ak1[9], av1[9];
#pragma unroll
    for (int j = 0; j < 9; ++j) {
        ak0[j] = INF; av0[j] = 0.f;
        ak1[j] = INF; av1[j] = 0.f;
    }

#pragma unroll 1
    for (int dy = 0; dy < 7; ++dy) {
        const float4* row = &tile[ty + dy][tx];
#pragma unroll
        for (int dx = 0; dx < 7; ++dx) {
            float4 p = row[dx];

            // Echo 0 distance: no FMA contraction (match XLA mul/add rounding),
            // IEEE sqrt (match jnp.sqrt) so ordering is bit-identical.
            float d0x = __fadd_rn(q0x, -p.x);
            float d0y = __fadd_rn(q0y, -p.y);
            float d0z = __fadd_rn(q0z, -p.z);
            float s0 = __fadd_rn(__fadd_rn(__fmul_rn(d0x, d0x), __fmul_rn(d0y, d0y)),
                                 __fmul_rn(d0z, d0z));
            float dist0 = __fsqrt_rn(s0);
            ins9_fma(dist0, p.w, ak0, av0);   // fma-pipe payload path

            // Echo 1
            float d1x = __fadd_rn(q1x, -p.x);
            float d1y = __fadd_rn(q1y, -p.y);
            float d1z = __fadd_rn(q1z, -p.z);
            float s1 = __fadd_rn(__fadd_rn(__fmul_rn(d1x, d1x), __fmul_rn(d1y, d1y)),
                                 __fmul_rn(d1z, d1z));
            float dist1 = __fsqrt_rn(s1);
            ins9_alu(dist1, p.w, ak1, av1);   // alu-pipe select path
        }
    }

    // Features: payloads already sorted in rank order — no gather needed.
    float feats[20];
#pragma unroll
    for (int s = 0; s < 9; ++s) {
        feats[s]      = av0[s];
        feats[10 + s] = av1[s];
    }
    feats[9]  = c4.w;  // center range ch0
    feats[19] = r1c;   // center range ch1

    // 20 -> 32 linear
    float acc[32];
#pragma unroll
    for (int k = 0; k < 32; ++k) acc[k] = 0.f;
#pragma unroll
    for (int c = 0; c < 20; ++c) {
        float f = feats[c];
        const float4* wp = (const float4*)&wt[c][0];
#pragma unroll
        for (int k4 = 0; k4 < 8; ++k4) {
            float4 wv = wp[k4];
            acc[k4 * 4 + 0] += f * wv.x;
            acc[k4 * 4 + 1] += f * wv.y;
            acc[k4 * 4 + 2] += f * wv.z;
            acc[k4 * 4 + 3] += f * wv.w;
        }
    }

    float* O = out + (size_t)b * 32 * HWP + pix;
#pragma unroll
    for (int k = 0; k < 32; ++k) {
        float v = acc[k];
        // leaky_relu(0.01): max(v, 0.01v) == leaky for both signs.
        v = fmaxf(v, 0.01f * v);
        O[(size_t)k * HWP] = v;
    }
}

extern "C" void kernel_launch(void* const* d_in, const int* in_sizes, int n_in,
                              void* d_out, int out_size) {
    const float* x  = (const float*)d_in[0];
    const float* rw = (const float*)d_in[1];
    // Defensive: identify the 640-element weight tensor by size.
    if (n_in >= 2 && in_sizes[0] == 640) {
        const float* t = x; x = rw; rw = t;
    }
    dim3 grid(WW / BX, HH / BY, 4);
    knn_block_kernel<<<grid, TPB>>>(x, rw, (float*)d_out);
}